// round 7
// baseline (speedup 1.0000x reference)
#include <cuda_runtime.h>
#include <cstdint>

#define NUM_EXPERTS 64
#define TOP_K 4
#define EMA_DECAY 0.99f
#define NBINS (NUM_EXPERTS * NUM_EXPERTS)
#define NCTAS 304
#define NTHREADS 512

// Ordered-pair histogram scratch: P[a*64+b] over tokens, pairs (k1<k2),
// a = idx[k1], b = idx[k2]. Symmetric coact = P + P^T.
// INVARIANT: g_P == 0 and g_done == 0 at every kernel entry.
//  - first execution: static zero-initialization
//  - later executions: the finalizing CTA re-zeroes g_P; atomicInc wraps g_done to 0
__device__ unsigned int g_P[NBINS];
__device__ unsigned int g_done;

// ---------------------------------------------------------------------------
// Single fused kernel: histogram + last-CTA finalize (no separate launches).
// Indices are int32 [N,4] row-major -> one int4 load per token.
// ---------------------------------------------------------------------------
__global__ void __launch_bounds__(NTHREADS, 2)
fused_tracker_kernel(const int4* __restrict__ idx,
                     const float* __restrict__ ema_in,
                     const float* __restrict__ coact_in,
                     float* __restrict__ out,
                     unsigned ntok) {
    __shared__ unsigned int sP[NBINS];
    __shared__ unsigned int sIsLast;

    for (int i = threadIdx.x; i < NBINS; i += NTHREADS) sP[i] = 0u;
    __syncthreads();

    const unsigned tid    = blockIdx.x * NTHREADS + threadIdx.x;
    const unsigned stride = gridDim.x * NTHREADS;

    // --- main loop: 2 tokens per iteration (MLP=2, amortized loop overhead) ---
    const unsigned half = ntok >> 1;
    for (unsigned pt = tid; pt < half; pt += stride) {
        int4 va = idx[2u * pt];
        int4 vb = idx[2u * pt + 1u];

        unsigned a0 = (unsigned)va.x, a1 = (unsigned)va.y;
        unsigned a2 = (unsigned)va.z, a3 = (unsigned)va.w;
        unsigned b0 = (unsigned)vb.x, b1 = (unsigned)vb.y;
        unsigned b2 = (unsigned)vb.z, b3 = (unsigned)vb.w;

        atomicAdd(&sP[(a0 << 6) + a1], 1u);
        atomicAdd(&sP[(a0 << 6) + a2], 1u);
        atomicAdd(&sP[(a0 << 6) + a3], 1u);
        atomicAdd(&sP[(a1 << 6) + a2], 1u);
        atomicAdd(&sP[(a1 << 6) + a3], 1u);
        atomicAdd(&sP[(a2 << 6) + a3], 1u);

        atomicAdd(&sP[(b0 << 6) + b1], 1u);
        atomicAdd(&sP[(b0 << 6) + b2], 1u);
        atomicAdd(&sP[(b0 << 6) + b3], 1u);
        atomicAdd(&sP[(b1 << 6) + b2], 1u);
        atomicAdd(&sP[(b1 << 6) + b3], 1u);
        atomicAdd(&sP[(b2 << 6) + b3], 1u);
    }
    // tail token if ntok is odd
    for (unsigned t = (half << 1) + tid; t < ntok; t += stride) {
        int4 v = idx[t];
        unsigned e0 = (unsigned)v.x, e1 = (unsigned)v.y;
        unsigned e2 = (unsigned)v.z, e3 = (unsigned)v.w;
        atomicAdd(&sP[(e0 << 6) + e1], 1u);
        atomicAdd(&sP[(e0 << 6) + e2], 1u);
        atomicAdd(&sP[(e0 << 6) + e3], 1u);
        atomicAdd(&sP[(e1 << 6) + e2], 1u);
        atomicAdd(&sP[(e1 << 6) + e3], 1u);
        atomicAdd(&sP[(e2 << 6) + e3], 1u);
    }
    __syncthreads();

    // --- flush CTA-local histogram to global scratch ---
    for (int i = threadIdx.x; i < NBINS; i += NTHREADS) {
        unsigned v = sP[i];
        if (v) atomicAdd(&g_P[i], v);
    }

    // --- last-CTA-done election (atomicInc self-wraps to 0 for next replay) ---
    __threadfence();
    __syncthreads();
    if (threadIdx.x == 0)
        sIsLast = (atomicInc(&g_done, gridDim.x - 1u) == gridDim.x - 1u) ? 1u : 0u;
    __syncthreads();
    if (!sIsLast) return;

    // --- finalize (only the last CTA): stage g_P -> sP, zero g_P for replay ---
    for (int i = threadIdx.x; i < NBINS; i += NTHREADS) {
        unsigned v = __ldcg(&g_P[i]);   // L2-coherent with the atomics
        sP[i] = v;
        g_P[i] = 0u;                    // restore invariant for next execution
    }
    __syncthreads();

    // coact output: coact_in + P + P^T   (integer-exact in fp32)
    for (int i = threadIdx.x; i < NBINS; i += NTHREADS) {
        int a = i >> 6;
        int b = i & 63;
        out[NUM_EXPERTS + i] =
            coact_in[i] + (float)(sP[(a << 6) + b] + sP[(b << 6) + a]);
    }

    // load EMA: 3*count[e] = rowsum(P)[e] + colsum(P)[e]  (K-1 = 3 pairs/occurrence)
    if (threadIdx.x < NUM_EXPERTS) {
        int e = threadIdx.x;
        unsigned s = 0u;
        #pragma unroll
        for (int j = 0; j < NUM_EXPERTS; j++) {
            s += sP[(e << 6) + j];
            s += sP[(j << 6) + e];
        }
        float count = (float)(s / 3u);          // exactly divisible by 3
        float load = count / (float)ntok;
        out[e] = ema_in[e] * EMA_DECAY + load * (1.0f - EMA_DECAY);
    }
}

// ---------------------------------------------------------------------------
// kernel_launch: ONE launch, graph-capturable, alloc-free.
// Inputs (metadata order):
//   d_in[0] expert_indices        int32  [N,4]
//   d_in[1] expert_weights        f32    [N,4]   (UNUSED by reference)
//   d_in[2] expert_load_ema       f32    [64]
//   d_in[3] expert_pair_coact     f32    [64,64]
// Output: f32 [64 + 4096] = (new_load_ema, new_coact) concatenated.
// ---------------------------------------------------------------------------
extern "C" void kernel_launch(void* const* d_in, const int* in_sizes, int n_in,
                              void* d_out, int out_size) {
    const int4* idx       = (const int4*)d_in[0];
    const float* ema_in   = (const float*)d_in[2];
    const float* coact_in = (const float*)d_in[3];
    float* out = (float*)d_out;

    unsigned ntok = (unsigned)(in_sizes[0] / TOP_K);

    // 304 CTAs x 512 threads: 2 CTAs/SM resident on 148/152-SM parts.
    fused_tracker_kernel<<<NCTAS, NTHREADS>>>(idx, ema_in, coact_in, out, ntok);
}

// round 8
// speedup vs baseline: 1.0845x; 1.0845x over previous
#include <cuda_runtime.h>
#include <cstdint>

#define NUM_EXPERTS 64
#define TOP_K 4
#define EMA_DECAY 0.99f
#define NBINS (NUM_EXPERTS * NUM_EXPERTS)
#define NCTAS 296            // 2 CTAs/SM on 148 SMs
#define NTHREADS 1024        // 2048 threads/SM resident -> ~100% occupancy

// Ordered-pair histogram scratch: P[a*64+b] over tokens, pairs (k1<k2),
// a = idx[k1], b = idx[k2]. Symmetric coact = P + P^T.
// INVARIANT: g_P == 0 and g_done == 0 at every kernel entry.
//  - first execution: static zero-initialization
//  - later executions: finalizing CTA re-zeroes g_P; atomicInc wraps g_done to 0
__device__ unsigned int g_P[NBINS];
__device__ unsigned int g_done;

// ---------------------------------------------------------------------------
// Single fused kernel: histogram + last-CTA finalize.
// Indices are int32 [N,4] row-major -> one int4 (16B) load per token.
// ---------------------------------------------------------------------------
__global__ void __launch_bounds__(NTHREADS, 2)
fused_tracker_kernel(const int4* __restrict__ idx,
                     const float* __restrict__ ema_in,
                     const float* __restrict__ coact_in,
                     float* __restrict__ out,
                     unsigned ntok) {
    __shared__ unsigned int sP[NBINS];
    __shared__ unsigned int sIsLast;

    for (int i = threadIdx.x; i < NBINS; i += NTHREADS) sP[i] = 0u;
    __syncthreads();

    const unsigned tid    = blockIdx.x * NTHREADS + threadIdx.x;
    const unsigned stride = gridDim.x * NTHREADS;

    // --- main loop: 2 tokens per iteration (front-batched LDG.128 x2) ---
    const unsigned half = ntok >> 1;
    for (unsigned pt = tid; pt < half; pt += stride) {
        int4 va = idx[2u * pt];
        int4 vb = idx[2u * pt + 1u];

        unsigned a0 = (unsigned)va.x, a1 = (unsigned)va.y;
        unsigned a2 = (unsigned)va.z, a3 = (unsigned)va.w;
        unsigned b0 = (unsigned)vb.x, b1 = (unsigned)vb.y;
        unsigned b2 = (unsigned)vb.z, b3 = (unsigned)vb.w;

        atomicAdd(&sP[(a0 << 6) + a1], 1u);
        atomicAdd(&sP[(a0 << 6) + a2], 1u);
        atomicAdd(&sP[(a0 << 6) + a3], 1u);
        atomicAdd(&sP[(a1 << 6) + a2], 1u);
        atomicAdd(&sP[(a1 << 6) + a3], 1u);
        atomicAdd(&sP[(a2 << 6) + a3], 1u);

        atomicAdd(&sP[(b0 << 6) + b1], 1u);
        atomicAdd(&sP[(b0 << 6) + b2], 1u);
        atomicAdd(&sP[(b0 << 6) + b3], 1u);
        atomicAdd(&sP[(b1 << 6) + b2], 1u);
        atomicAdd(&sP[(b1 << 6) + b3], 1u);
        atomicAdd(&sP[(b2 << 6) + b3], 1u);
    }
    // tail token if ntok is odd
    for (unsigned t = (half << 1) + tid; t < ntok; t += stride) {
        int4 v = idx[t];
        unsigned e0 = (unsigned)v.x, e1 = (unsigned)v.y;
        unsigned e2 = (unsigned)v.z, e3 = (unsigned)v.w;
        atomicAdd(&sP[(e0 << 6) + e1], 1u);
        atomicAdd(&sP[(e0 << 6) + e2], 1u);
        atomicAdd(&sP[(e0 << 6) + e3], 1u);
        atomicAdd(&sP[(e1 << 6) + e2], 1u);
        atomicAdd(&sP[(e1 << 6) + e3], 1u);
        atomicAdd(&sP[(e2 << 6) + e3], 1u);
    }
    __syncthreads();

    // --- flush CTA-local histogram to global scratch (4 bins/thread) ---
    for (int i = threadIdx.x; i < NBINS; i += NTHREADS) {
        unsigned v = sP[i];
        if (v) atomicAdd(&g_P[i], v);
    }

    // --- last-CTA election (atomicInc self-wraps to 0 for next replay) ---
    __threadfence();
    __syncthreads();
    if (threadIdx.x == 0)
        sIsLast = (atomicInc(&g_done, gridDim.x - 1u) == gridDim.x - 1u) ? 1u : 0u;
    __syncthreads();
    if (!sIsLast) return;

    // --- finalize (last CTA only): stage g_P -> sP, zero g_P for next replay ---
    for (int i = threadIdx.x; i < NBINS; i += NTHREADS) {
        unsigned v = __ldcg(&g_P[i]);   // L2-coherent with the atomics
        sP[i] = v;
        g_P[i] = 0u;                    // restore invariant
    }
    __syncthreads();

    // coact output: coact_in + P + P^T   (integer-exact in fp32)
    for (int i = threadIdx.x; i < NBINS; i += NTHREADS) {
        int a = i >> 6;
        int b = i & 63;
        out[NUM_EXPERTS + i] =
            coact_in[i] + (float)(sP[(a << 6) + b] + sP[(b << 6) + a]);
    }

    // load EMA: 3*count[e] = rowsum(P)[e] + colsum(P)[e]  (K-1 = 3 pairs/occurrence)
    if (threadIdx.x < NUM_EXPERTS) {
        int e = threadIdx.x;
        unsigned s = 0u;
        #pragma unroll
        for (int j = 0; j < NUM_EXPERTS; j++) {
            s += sP[(e << 6) + j];
            s += sP[(j << 6) + e];
        }
        float count = (float)(s / 3u);          // exactly divisible by 3
        float load = count / (float)ntok;
        out[e] = ema_in[e] * EMA_DECAY + load * (1.0f - EMA_DECAY);
    }
}

// ---------------------------------------------------------------------------
// kernel_launch: ONE launch, graph-capturable, alloc-free.
// Inputs (metadata order):
//   d_in[0] expert_indices        int32  [N,4]
//   d_in[1] expert_weights        f32    [N,4]   (UNUSED by reference)
//   d_in[2] expert_load_ema       f32    [64]
//   d_in[3] expert_pair_coact     f32    [64,64]
// Output: f32 [64 + 4096] = (new_load_ema, new_coact) concatenated.
// ---------------------------------------------------------------------------
extern "C" void kernel_launch(void* const* d_in, const int* in_sizes, int n_in,
                              void* d_out, int out_size) {
    const int4* idx       = (const int4*)d_in[0];
    const float* ema_in   = (const float*)d_in[2];
    const float* coact_in = (const float*)d_in[3];
    float* out = (float*)d_out;

    unsigned ntok = (unsigned)(in_sizes[0] / TOP_K);

    fused_tracker_kernel<<<NCTAS, NTHREADS>>>(idx, ema_in, coact_in, out, ntok);
}

// round 11
// speedup vs baseline: 1.1983x; 1.1050x over previous
#include <cuda_runtime.h>
#include <cstdint>

#define NUM_EXPERTS 64
#define TOP_K 4
#define EMA_DECAY 0.99f
#define NBINS (NUM_EXPERTS * NUM_EXPERTS)
#define NCTAS 296            // 2 CTAs/SM on 148 SMs
#define NTHREADS 1024        // 2048 threads/SM -> ~full occupancy

// Ordered-pair histogram scratch: P[a*64+b] over tokens, pairs (k1<k2).
// Symmetric coact = P + P^T.
// INVARIANT at kernel entry: g_P == 0, g_done == 0.
//  - first execution: static zero-init
//  - later executions: finalizing CTA re-zeroes g_P; atomicInc wraps g_done
__device__ unsigned int g_P[NBINS];
__device__ unsigned int g_done;

__device__ __forceinline__ uint32_t smem_addr_u32(const void* p) {
    uint32_t a;
    asm("{ .reg .u64 t; cvta.to.shared.u64 t, %1; cvt.u32.u64 %0, t; }"
        : "=r"(a) : "l"(p));
    return a;
}

// No-return shared reduction: ATOMS with no destination -> NO scoreboard wbar,
// fire-and-forget like a store. This is the whole point of this round.
__device__ __forceinline__ void red_shared_inc(uint32_t byte_addr) {
    asm volatile("red.shared.add.u32 [%0], %1;" :: "r"(byte_addr), "r"(1u) : "memory");
}
// No-return global reduction (REDG).
__device__ __forceinline__ void red_global_add(unsigned int* p, unsigned int v) {
    asm volatile("red.global.add.u32 [%0], %1;" :: "l"(p), "r"(v) : "memory");
}

// ---------------------------------------------------------------------------
// Single fused kernel: histogram (red.shared) + last-CTA finalize.
// Indices are int32 [N,4] row-major -> one int4 (16B) load per token.
// ---------------------------------------------------------------------------
__global__ void __launch_bounds__(NTHREADS, 2)
fused_tracker_kernel(const int4* __restrict__ idx,
                     const float* __restrict__ ema_in,
                     const float* __restrict__ coact_in,
                     float* __restrict__ out,
                     unsigned ntok) {
    __shared__ unsigned int sP[NBINS];
    __shared__ unsigned int sIsLast;

    for (int i = threadIdx.x; i < NBINS; i += NTHREADS) sP[i] = 0u;
    __syncthreads();

    const uint32_t sbase = smem_addr_u32(sP);   // byte address of sP[0]

    const unsigned tid    = blockIdx.x * NTHREADS + threadIdx.x;
    const unsigned stride = gridDim.x * NTHREADS;

    // --- main loop: 2 tokens per iteration (front-batched LDG.128 x2) ---
    const unsigned half = ntok >> 1;
    for (unsigned pt = tid; pt < half; pt += stride) {
        int4 va = idx[2u * pt];
        int4 vb = idx[2u * pt + 1u];

        // byte offsets: pair (x,y) -> ((x<<6)+y)<<2 = (x<<8) + (y<<2)
        uint32_t a0 = (uint32_t)va.x << 8, a1 = (uint32_t)va.y << 8;
        uint32_t a2 = (uint32_t)va.z << 8, a3s = (uint32_t)va.w << 2;
        uint32_t a1s = a1 >> 6, a2s = a2 >> 6;   // y<<2 forms
        uint32_t b0 = (uint32_t)vb.x << 8, b1 = (uint32_t)vb.y << 8;
        uint32_t b2 = (uint32_t)vb.z << 8, b3s = (uint32_t)vb.w << 2;
        uint32_t b1s = b1 >> 6, b2s = b2 >> 6;

        red_shared_inc(sbase + a0 + a1s);
        red_shared_inc(sbase + a0 + a2s);
        red_shared_inc(sbase + a0 + a3s);
        red_shared_inc(sbase + a1 + a2s);
        red_shared_inc(sbase + a1 + a3s);
        red_shared_inc(sbase + a2 + a3s);

        red_shared_inc(sbase + b0 + b1s);
        red_shared_inc(sbase + b0 + b2s);
        red_shared_inc(sbase + b0 + b3s);
        red_shared_inc(sbase + b1 + b2s);
        red_shared_inc(sbase + b1 + b3s);
        red_shared_inc(sbase + b2 + b3s);
    }
    // tail token if ntok is odd
    for (unsigned t = (half << 1) + tid; t < ntok; t += stride) {
        int4 v = idx[t];
        uint32_t e0 = (uint32_t)v.x << 8, e1 = (uint32_t)v.y << 8;
        uint32_t e2 = (uint32_t)v.z << 8, e3s = (uint32_t)v.w << 2;
        uint32_t e1s = e1 >> 6, e2s = e2 >> 6;
        red_shared_inc(sbase + e0 + e1s);
        red_shared_inc(sbase + e0 + e2s);
        red_shared_inc(sbase + e0 + e3s);
        red_shared_inc(sbase + e1 + e2s);
        red_shared_inc(sbase + e1 + e3s);
        red_shared_inc(sbase + e2 + e3s);
    }
    __syncthreads();   // BAR drains pending shared reductions (HW-native)

    // --- flush CTA-local histogram to global scratch (REDG, no return) ---
    for (int i = threadIdx.x; i < NBINS; i += NTHREADS) {
        unsigned v = sP[i];
        if (v) red_global_add(&g_P[i], v);
    }

    // --- last-CTA election (atomicInc self-wraps to 0 for next replay) ---
    __threadfence();   // order REDGs before the done-count
    __syncthreads();
    if (threadIdx.x == 0)
        sIsLast = (atomicInc(&g_done, gridDim.x - 1u) == gridDim.x - 1u) ? 1u : 0u;
    __syncthreads();
    if (!sIsLast) return;

    // --- finalize (last CTA only): stage g_P -> sP, zero g_P for next replay ---
    for (int i = threadIdx.x; i < NBINS; i += NTHREADS) {
        unsigned v = __ldcg(&g_P[i]);   // L2-coherent with the reductions
        sP[i] = v;
        g_P[i] = 0u;                    // restore invariant
    }
    __syncthreads();

    // coact output: coact_in + P + P^T   (integer-exact in fp32)
    for (int i = threadIdx.x; i < NBINS; i += NTHREADS) {
        int a = i >> 6;
        int b = i & 63;
        out[NUM_EXPERTS + i] =
            coact_in[i] + (float)(sP[(a << 6) + b] + sP[(b << 6) + a]);
    }

    // load EMA: 3*count[e] = rowsum(P)[e] + colsum(P)[e]  (K-1 = 3 pairs/occurrence)
    if (threadIdx.x < NUM_EXPERTS) {
        int e = threadIdx.x;
        unsigned s = 0u;
        #pragma unroll
        for (int j = 0; j < NUM_EXPERTS; j++) {
            s += sP[(e << 6) + j];
            s += sP[(j << 6) + e];
        }
        float count = (float)(s / 3u);          // exactly divisible by 3
        float load = count / (float)ntok;
        out[e] = ema_in[e] * EMA_DECAY + load * (1.0f - EMA_DECAY);
    }
}

// ---------------------------------------------------------------------------
// kernel_launch: ONE launch, graph-capturable, alloc-free.
// Inputs (metadata order):
//   d_in[0] expert_indices        int32  [N,4]
//   d_in[1] expert_weights        f32    [N,4]   (UNUSED by reference)
//   d_in[2] expert_load_ema       f32    [64]
//   d_in[3] expert_pair_coact     f32    [64,64]
// Output: f32 [64 + 4096] = (new_load_ema, new_coact) concatenated.
// ---------------------------------------------------------------------------
extern "C" void kernel_launch(void* const* d_in, const int* in_sizes, int n_in,
                              void* d_out, int out_size) {
    const int4* idx       = (const int4*)d_in[0];
    const float* ema_in   = (const float*)d_in[2];
    const float* coact_in = (const float*)d_in[3];
    float* out = (float*)d_out;

    unsigned ntok = (unsigned)(in_sizes[0] / TOP_K);

    fused_tracker_kernel<<<NCTAS, NTHREADS>>>(idx, ema_in, coact_in, out, ntok);
}